// round 1
// baseline (speedup 1.0000x reference)
#include <cuda_runtime.h>

#define LQ 512
#define LLQ (512*512)

// channel-major scratch: [c][row] with row = flattened (i*L+m) / (m*L+j) / (i*L+j)
__device__ float g_a[(size_t)128 * LLQ];
__device__ float g_b[(size_t)128 * LLQ];
__device__ float g_k[(size_t)128 * LLQ];

__device__ __forceinline__ float sigmoidf_(float x) {
    return 1.0f / (1.0f + __expf(-x));
}

// ---------------------------------------------------------------------------
// Kernel 1: LN(z) + 4 gated projections -> a,b in channel-major layout
// block = 128 rows of the flattened [L*L, 128] input, 256 threads
// ---------------------------------------------------------------------------
__global__ void __launch_bounds__(256) k_ln_proj_ab(
    const float* __restrict__ z,
    const float* __restrict__ lnw, const float* __restrict__ lnb,
    const float* __restrict__ Wga, const float* __restrict__ bga,
    const float* __restrict__ Wla, const float* __restrict__ bla,
    const float* __restrict__ Wgb, const float* __restrict__ bgb,
    const float* __restrict__ Wlb, const float* __restrict__ blb)
{
    extern __shared__ float sm[];
    float* zn = sm;                  // [128][129]
    float* Ws = sm + 128 * 129;      // [128][128]
    float* sc = Ws + 128 * 128;      // [128][129]

    const int tid  = threadIdx.x;
    const int r0   = blockIdx.x * 128;
    const int lane = tid & 31, warp = tid >> 5;

    // ---- layernorm: one warp per row, 16 rows per warp ----
    const float w0 = lnw[lane], w1 = lnw[lane + 32], w2 = lnw[lane + 64], w3 = lnw[lane + 96];
    const float c0 = lnb[lane], c1 = lnb[lane + 32], c2 = lnb[lane + 64], c3 = lnb[lane + 96];
    for (int it = 0; it < 16; ++it) {
        int row = warp * 16 + it;
        const float* zr = z + (size_t)(r0 + row) * 128;
        float x0 = zr[lane], x1 = zr[lane + 32], x2 = zr[lane + 64], x3 = zr[lane + 96];
        float s = x0 + x1 + x2 + x3;
        float q = x0 * x0 + x1 * x1 + x2 * x2 + x3 * x3;
        #pragma unroll
        for (int o = 16; o > 0; o >>= 1) {
            s += __shfl_xor_sync(0xffffffffu, s, o);
            q += __shfl_xor_sync(0xffffffffu, q, o);
        }
        float mu  = s * (1.0f / 128.0f);
        float var = q * (1.0f / 128.0f) - mu * mu;
        float rs  = rsqrtf(var + 1e-5f);
        float* zo = zn + row * 129;
        zo[lane]      = (x0 - mu) * rs * w0 + c0;
        zo[lane + 32] = (x1 - mu) * rs * w1 + c1;
        zo[lane + 64] = (x2 - mu) * rs * w2 + c2;
        zo[lane + 96] = (x3 - mu) * rs * w3 + c3;
    }
    __syncthreads();

    const int tx = tid & 15, ty = tid >> 4;
    const int mb = ty * 8, cb = tx * 8;
    const float* znr = zn + mb * 129;

    #pragma unroll 1
    for (int p = 0; p < 2; ++p) {
        const float* Wg = p ? Wgb : Wga;
        const float* bg = p ? bgb : bga;
        const float* Wl = p ? Wlb : Wla;
        const float* bl = p ? blb : bla;
        float* dst = p ? g_b : g_a;

        // load gate weight
        for (int it = 0; it < 64; ++it) { int idx = it * 256 + tid; Ws[idx] = Wg[idx]; }
        __syncthreads();

        float acc[8][8];
        #pragma unroll
        for (int e = 0; e < 8; ++e)
            #pragma unroll
            for (int f = 0; f < 8; ++f) acc[e][f] = 0.0f;

        #pragma unroll 4
        for (int k = 0; k < 128; ++k) {
            float av[8];
            #pragma unroll
            for (int e = 0; e < 8; ++e) av[e] = znr[e * 129 + k];
            float4 q0 = *(const float4*)(Ws + k * 128 + cb);
            float4 q1 = *(const float4*)(Ws + k * 128 + cb + 4);
            float bv[8] = {q0.x, q0.y, q0.z, q0.w, q1.x, q1.y, q1.z, q1.w};
            #pragma unroll
            for (int e = 0; e < 8; ++e)
                #pragma unroll
                for (int f = 0; f < 8; ++f) acc[e][f] += av[e] * bv[f];
        }
        __syncthreads();   // Ws reads done everywhere

        {
            float bgv[8];
            #pragma unroll
            for (int f = 0; f < 8; ++f) bgv[f] = bg[cb + f];
            #pragma unroll
            for (int e = 0; e < 8; ++e)
                #pragma unroll
                for (int f = 0; f < 8; ++f)
                    sc[(mb + e) * 129 + cb + f] = sigmoidf_(acc[e][f] + bgv[f]);
        }
        // reload linear weight
        for (int it = 0; it < 64; ++it) { int idx = it * 256 + tid; Ws[idx] = Wl[idx]; }
        __syncthreads();

        #pragma unroll
        for (int e = 0; e < 8; ++e)
            #pragma unroll
            for (int f = 0; f < 8; ++f) acc[e][f] = 0.0f;

        #pragma unroll 4
        for (int k = 0; k < 128; ++k) {
            float av[8];
            #pragma unroll
            for (int e = 0; e < 8; ++e) av[e] = znr[e * 129 + k];
            float4 q0 = *(const float4*)(Ws + k * 128 + cb);
            float4 q1 = *(const float4*)(Ws + k * 128 + cb + 4);
            float bv[8] = {q0.x, q0.y, q0.z, q0.w, q1.x, q1.y, q1.z, q1.w};
            #pragma unroll
            for (int e = 0; e < 8; ++e)
                #pragma unroll
                for (int f = 0; f < 8; ++f) acc[e][f] += av[e] * bv[f];
        }

        {
            float blv[8];
            #pragma unroll
            for (int f = 0; f < 8; ++f) blv[f] = bl[cb + f];
            #pragma unroll
            for (int e = 0; e < 8; ++e)
                #pragma unroll
                for (int f = 0; f < 8; ++f) {
                    int s_idx = (mb + e) * 129 + cb + f;
                    sc[s_idx] = sc[s_idx] * (acc[e][f] + blv[f]);   // own slot, no race
                }
        }
        __syncthreads();

        // transposed, coalesced store: dst[c*LL + r0 + m]
        for (int it = 0; it < 64; ++it) {
            int idx = it * 256 + tid;
            int m = idx & 127;
            int c = idx >> 7;
            dst[(size_t)c * LLQ + r0 + m] = sc[m * 129 + c];
        }
        __syncthreads();
    }
}

// ---------------------------------------------------------------------------
// Kernel 2: per-channel 512x512x512 GEMM  K_c = A_c @ B_c (row-major, contiguous)
// BM=BN=128, BK=16, 256 threads, 8x8 per thread
// ---------------------------------------------------------------------------
__global__ void __launch_bounds__(256) k_einsum()
{
    __shared__ float As[128 * 17];
    __shared__ float Bs[16 * 128];

    const int c  = blockIdx.z;
    const int i0 = blockIdx.y * 128;
    const int j0 = blockIdx.x * 128;
    const float* A = g_a + (size_t)c * LLQ;
    const float* B = g_b + (size_t)c * LLQ;
    float*       K = g_k + (size_t)c * LLQ;

    const int tid = threadIdx.x;
    const int tx = tid & 15, ty = tid >> 4;

    const int arow = tid >> 1,  acol = (tid & 1) * 8;
    const int brow = tid >> 4,  bcol = (tid & 15) * 8;

    float acc[8][8];
    #pragma unroll
    for (int e = 0; e < 8; ++e)
        #pragma unroll
        for (int f = 0; f < 8; ++f) acc[e][f] = 0.0f;

    for (int kt = 0; kt < 32; ++kt) {
        int k0 = kt * 16;
        float4 a0 = *(const float4*)(A + (size_t)(i0 + arow) * LQ + k0 + acol);
        float4 a1 = *(const float4*)(A + (size_t)(i0 + arow) * LQ + k0 + acol + 4);
        float* asr = As + arow * 17 + acol;
        asr[0] = a0.x; asr[1] = a0.y; asr[2] = a0.z; asr[3] = a0.w;
        asr[4] = a1.x; asr[5] = a1.y; asr[6] = a1.z; asr[7] = a1.w;

        float4 v0 = *(const float4*)(B + (size_t)(k0 + brow) * LQ + j0 + bcol);
        float4 v1 = *(const float4*)(B + (size_t)(k0 + brow) * LQ + j0 + bcol + 4);
        *(float4*)(Bs + brow * 128 + bcol)     = v0;
        *(float4*)(Bs + brow * 128 + bcol + 4) = v1;
        __syncthreads();

        const float* asb = As + ty * 8 * 17;
        #pragma unroll
        for (int k = 0; k < 16; ++k) {
            float av[8];
            #pragma unroll
            for (int e = 0; e < 8; ++e) av[e] = asb[e * 17 + k];
            float4 q0 = *(const float4*)(Bs + k * 128 + tx * 8);
            float4 q1 = *(const float4*)(Bs + k * 128 + tx * 8 + 4);
            float bv[8] = {q0.x, q0.y, q0.z, q0.w, q1.x, q1.y, q1.z, q1.w};
            #pragma unroll
            for (int e = 0; e < 8; ++e)
                #pragma unroll
                for (int f = 0; f < 8; ++f) acc[e][f] += av[e] * bv[f];
        }
        __syncthreads();
    }

    #pragma unroll
    for (int e = 0; e < 8; ++e) {
        float* kr = K + (size_t)(i0 + ty * 8 + e) * LQ + j0 + tx * 8;
        float4 o0 = make_float4(acc[e][0], acc[e][1], acc[e][2], acc[e][3]);
        float4 o1 = make_float4(acc[e][4], acc[e][5], acc[e][6], acc[e][7]);
        *(float4*)(kr)     = o0;
        *(float4*)(kr + 4) = o1;
    }
}

// ---------------------------------------------------------------------------
// Kernel 3: out = sigmoid(LN(z)@Wgo + bgo) * (LN(k)@Wlo + blo)
// ---------------------------------------------------------------------------
__global__ void __launch_bounds__(256) k_final(
    const float* __restrict__ z,
    const float* __restrict__ lnw, const float* __restrict__ lnb,
    const float* __restrict__ lnow, const float* __restrict__ lnob,
    const float* __restrict__ Wgo, const float* __restrict__ bgo,
    const float* __restrict__ Wlo, const float* __restrict__ blo,
    float* __restrict__ out)
{
    extern __shared__ float sm[];
    float* zn = sm;                  // [128][129]  (later reused to hold the gate)
    float* kn = sm + 128 * 129;      // [128][129]
    float* Ws = kn + 128 * 129;      // [128][128]

    const int tid  = threadIdx.x;
    const int r0   = blockIdx.x * 128;
    const int i    = r0 >> 9;
    const int j0   = r0 & 511;
    const int lane = tid & 31, warp = tid >> 5;

    // LN(z)
    {
        const float w0 = lnw[lane], w1 = lnw[lane + 32], w2 = lnw[lane + 64], w3 = lnw[lane + 96];
        const float c0 = lnb[lane], c1 = lnb[lane + 32], c2 = lnb[lane + 64], c3 = lnb[lane + 96];
        for (int it = 0; it < 16; ++it) {
            int row = warp * 16 + it;
            const float* zr = z + (size_t)(r0 + row) * 128;
            float x0 = zr[lane], x1 = zr[lane + 32], x2 = zr[lane + 64], x3 = zr[lane + 96];
            float s = x0 + x1 + x2 + x3;
            float q = x0 * x0 + x1 * x1 + x2 * x2 + x3 * x3;
            #pragma unroll
            for (int o = 16; o > 0; o >>= 1) {
                s += __shfl_xor_sync(0xffffffffu, s, o);
                q += __shfl_xor_sync(0xffffffffu, q, o);
            }
            float mu  = s * (1.0f / 128.0f);
            float var = q * (1.0f / 128.0f) - mu * mu;
            float rs  = rsqrtf(var + 1e-5f);
            float* zo = zn + row * 129;
            zo[lane]      = (x0 - mu) * rs * w0 + c0;
            zo[lane + 32] = (x1 - mu) * rs * w1 + c1;
            zo[lane + 64] = (x2 - mu) * rs * w2 + c2;
            zo[lane + 96] = (x3 - mu) * rs * w3 + c3;
        }
    }

    // gather k tile from channel-major g_k -> kn[jl][c]
    for (int it = 0; it < 64; ++it) {
        int idx = it * 256 + tid;
        int jl = idx & 127;
        int c  = idx >> 7;
        kn[jl * 129 + c] = g_k[(size_t)c * LLQ + (size_t)i * LQ + j0 + jl];
    }
    __syncthreads();

    // LN(k) in place
    {
        const float w0 = lnow[lane], w1 = lnow[lane + 32], w2 = lnow[lane + 64], w3 = lnow[lane + 96];
        const float c0 = lnob[lane], c1 = lnob[lane + 32], c2 = lnob[lane + 64], c3 = lnob[lane + 96];
        for (int it = 0; it < 16; ++it) {
            int row = warp * 16 + it;
            float* kr = kn + row * 129;
            float x0 = kr[lane], x1 = kr[lane + 32], x2 = kr[lane + 64], x3 = kr[lane + 96];
            float s = x0 + x1 + x2 + x3;
            float q = x0 * x0 + x1 * x1 + x2 * x2 + x3 * x3;
            #pragma unroll
            for (int o = 16; o > 0; o >>= 1) {
                s += __shfl_xor_sync(0xffffffffu, s, o);
                q += __shfl_xor_sync(0xffffffffu, q, o);
            }
            float mu  = s * (1.0f / 128.0f);
            float var = q * (1.0f / 128.0f) - mu * mu;
            float rs  = rsqrtf(var + 1e-5f);
            kr[lane]      = (x0 - mu) * rs * w0 + c0;
            kr[lane + 32] = (x1 - mu) * rs * w1 + c1;
            kr[lane + 64] = (x2 - mu) * rs * w2 + c2;
            kr[lane + 96] = (x3 - mu) * rs * w3 + c3;
        }
    }

    const int tx = tid & 15, ty = tid >> 4;
    const int mb = ty * 8, cb = tx * 8;

    // gate GEMM: zn @ Wgo
    for (int it = 0; it < 64; ++it) { int idx = it * 256 + tid; Ws[idx] = Wgo[idx]; }
    __syncthreads();

    float acc[8][8];
    #pragma unroll
    for (int e = 0; e < 8; ++e)
        #pragma unroll
        for (int f = 0; f < 8; ++f) acc[e][f] = 0.0f;

    {
        const float* znr = zn + mb * 129;
        #pragma unroll 4
        for (int k = 0; k < 128; ++k) {
            float av[8];
            #pragma unroll
            for (int e = 0; e < 8; ++e) av[e] = znr[e * 129 + k];
            float4 q0 = *(const float4*)(Ws + k * 128 + cb);
            float4 q1 = *(const float4*)(Ws + k * 128 + cb + 4);
            float bv[8] = {q0.x, q0.y, q0.z, q0.w, q1.x, q1.y, q1.z, q1.w};
            #pragma unroll
            for (int e = 0; e < 8; ++e)
                #pragma unroll
                for (int f = 0; f < 8; ++f) acc[e][f] += av[e] * bv[f];
        }
    }
    __syncthreads();   // all zn reads + Ws reads done

    {
        float bgv[8];
        #pragma unroll
        for (int f = 0; f < 8; ++f) bgv[f] = bgo[cb + f];
        #pragma unroll
        for (int e = 0; e < 8; ++e)
            #pragma unroll
            for (int f = 0; f < 8; ++f)
                zn[(mb + e) * 129 + cb + f] = sigmoidf_(acc[e][f] + bgv[f]);  // zn now = gate
    }
    for (int it = 0; it < 64; ++it) { int idx = it * 256 + tid; Ws[idx] = Wlo[idx]; }
    __syncthreads();

    #pragma unroll
    for (int e = 0; e < 8; ++e)
        #pragma unroll
        for (int f = 0; f < 8; ++f) acc[e][f] = 0.0f;

    {
        const float* knr = kn + mb * 129;
        #pragma unroll 4
        for (int k = 0; k < 128; ++k) {
            float av[8];
            #pragma unroll
            for (int e = 0; e < 8; ++e) av[e] = knr[e * 129 + k];
            float4 q0 = *(const float4*)(Ws + k * 128 + cb);
            float4 q1 = *(const float4*)(Ws + k * 128 + cb + 4);
            float bv[8] = {q0.x, q0.y, q0.z, q0.w, q1.x, q1.y, q1.z, q1.w};
            #pragma unroll
            for (int e = 0; e < 8; ++e)
                #pragma unroll
                for (int f = 0; f < 8; ++f) acc[e][f] += av[e] * bv[f];
        }
    }

    {
        float blv[8];
        #pragma unroll
        for (int f = 0; f < 8; ++f) blv[f] = blo[cb + f];
        #pragma unroll
        for (int e = 0; e < 8; ++e) {
            float v[8];
            #pragma unroll
            for (int f = 0; f < 8; ++f)
                v[f] = zn[(mb + e) * 129 + cb + f] * (acc[e][f] + blv[f]);
            float* orow = out + (size_t)(r0 + mb + e) * 128 + cb;
            *(float4*)(orow)     = make_float4(v[0], v[1], v[2], v[3]);
            *(float4*)(orow + 4) = make_float4(v[4], v[5], v[6], v[7]);
        }
    }
}

// ---------------------------------------------------------------------------
extern "C" void kernel_launch(void* const* d_in, const int* in_sizes, int n_in,
                              void* d_out, int out_size)
{
    const float* z    = (const float*)d_in[0];
    const float* lnw  = (const float*)d_in[1];
    const float* lnb  = (const float*)d_in[2];
    const float* Wga  = (const float*)d_in[3];
    const float* bga  = (const float*)d_in[4];
    const float* Wla  = (const float*)d_in[5];
    const float* bla  = (const float*)d_in[6];
    const float* Wgb  = (const float*)d_in[7];
    const float* bgb  = (const float*)d_in[8];
    const float* Wlb  = (const float*)d_in[9];
    const float* blb  = (const float*)d_in[10];
    const float* lnow = (const float*)d_in[11];
    const float* lnob = (const float*)d_in[12];
    const float* Wgo  = (const float*)d_in[13];
    const float* bgo  = (const float*)d_in[14];
    const float* Wlo  = (const float*)d_in[15];
    const float* blo  = (const float*)d_in[16];
    float* out = (float*)d_out;

    const size_t smemA = (size_t)(128 * 129 + 128 * 128 + 128 * 129) * sizeof(float);
    cudaFuncSetAttribute(k_ln_proj_ab, cudaFuncAttributeMaxDynamicSharedMemorySize, (int)smemA);
    cudaFuncSetAttribute(k_final,      cudaFuncAttributeMaxDynamicSharedMemorySize, (int)smemA);

    k_ln_proj_ab<<<2048, 256, smemA>>>(z, lnw, lnb, Wga, bga, Wla, bla, Wgb, bgb, Wlb, blb);
    k_einsum<<<dim3(4, 4, 128), 256>>>();
    k_final<<<2048, 256, smemA>>>(z, lnw, lnb, lnow, lnob, Wgo, bgo, Wlo, blo, out);
}